// round 7
// baseline (speedup 1.0000x reference)
#include <cuda_runtime.h>
#include <cuda_fp16.h>
#include <math.h>

#define NBATCH 64
#define NCAT   128
#define NK     127
#define NTYPE  6
#define NCH    36
#define NUNIT  (NCAT * NK)       // 16256 (n,j) units
#define NSLOT  (NUNIT * 2)       // 32512 warp-slots (2 batch halves per unit)
#define NPLAN  (NSLOT + NCH * 4) // padded plan capacity
#define NBLK1  (NPLAN / 4)       // K1 blocks (4 warp-slots each)

// per-channel packed weight block layout (floats):
// [0,25)=W1*  [25,50)=b1*  [50,200)=unused
// [200,1600)=W2* rows padded to 28 (col25=b2*, col26,27=0)
// [1600,6800)=W3* rows padded to 52 (col50=b3*, col51=0)
// (* = pre-scaled by 2*log2(e) so tanh needs no input multiply)
#define CHW 6800
#define TSCL 2.885390081777927f

__device__ float  g_Wall[NCH * CHW];
__device__ int    g_plan[NPLAN];
__device__ __half g_out[(size_t)NBATCH * NCAT * NK * 100];  // MLP outputs (fp16)

// ---------------- f32x2 helpers ----------------
__device__ __forceinline__ unsigned long long pk2(float lo, float hi) {
    unsigned long long r;
    asm("mov.b64 %0, {%1, %2};" : "=l"(r) : "f"(lo), "f"(hi));
    return r;
}
__device__ __forceinline__ void unp2(unsigned long long v, float& lo, float& hi) {
    asm("mov.b64 {%0, %1}, %2;" : "=f"(lo), "=f"(hi) : "l"(v));
}
__device__ __forceinline__ unsigned long long fma2w(float wlo, float whi,
                                                    unsigned long long x,
                                                    unsigned long long acc) {
    unsigned long long w = pk2(wlo, whi);
    unsigned long long r;
    asm("fma.rn.f32x2 %0, %1, %2, %3;" : "=l"(r) : "l"(w), "l"(x), "l"(acc));
    return r;
}
// tanh on a PRE-SCALED input s = 2*log2e*v : 1 - 2*rcp(2^s + 1). 4 ops.
__device__ __forceinline__ float tanhS(float s) {
    float e;
    asm("ex2.approx.ftz.f32 %0, %1;" : "=f"(e) : "f"(s));
    float r;
    asm("rcp.approx.ftz.f32 %0, %1;" : "=f"(r) : "f"(e + 1.0f));
    return fmaf(-2.0f, r, 1.0f);
}

// ---------------- fused prep: weight pack (+scale, +bias-fold) & plan ----------------
__global__ void prep_all(const float* __restrict__ W1, const float* __restrict__ b1,
                         const float* __restrict__ W2, const float* __restrict__ b2,
                         const float* __restrict__ W3, const float* __restrict__ b3,
                         const int* __restrict__ types) {
    __shared__ int ts[NCAT];
    __shared__ int cnt[NCH];
    __shared__ int off[NCH];

    if (blockIdx.x == gridDim.x - 1) {
        // ---- plan block ----
        int t = threadIdx.x;
        for (int i = t; i < NPLAN; i += 256) g_plan[i] = -1;
        if (t < NCAT) ts[t] = types[t];
        if (t < NCH)  cnt[t] = 0;
        __syncthreads();
        for (int u = t; u < NUNIT; u += 256) {
            int n = u / NK, k = u % NK;
            int j = k + (k >= n ? 1 : 0);
            atomicAdd(&cnt[ts[n] * NTYPE + ts[j]], 2);
        }
        __syncthreads();
        if (t == 0) {
            int run = 0;
            for (int c = 0; c < NCH; c++) {
                off[c] = run;
                run += (cnt[c] + 3) & ~3;
            }
        }
        __syncthreads();
        for (int u = t; u < NUNIT; u += 256) {
            int n = u / NK, k = u % NK;
            int j = k + (k >= n ? 1 : 0);
            int c = ts[n] * NTYPE + ts[j];
            int pos = atomicAdd(&off[c], 2);
            g_plan[pos]     = u * 2;
            g_plan[pos + 1] = u * 2 + 1;
        }
        return;
    }

    // ---- pack blocks ----
    int i = blockIdx.x * blockDim.x + threadIdx.x;
    if (i >= NCH * CHW) return;
    int ch = i / CHW;
    int r  = i % CHW;
    float v = 0.0f;
    if (r < 25)        v = TSCL * W1[ch * 25 + r];
    else if (r < 50)   v = TSCL * b1[ch * 25 + (r - 25)];
    else if (r < 200)  v = 0.0f;
    else if (r < 1600) {
        int rr = r - 200, o = rr / 28, c = rr % 28;
        if (c < 25)       v = TSCL * W2[(ch * 50 + o) * 25 + c];
        else if (c == 25) v = TSCL * b2[ch * 50 + o];
        else              v = 0.0f;
    } else {
        int rr = r - 1600, o = rr / 52, c = rr % 52;
        if (c < 50)       v = TSCL * W3[(ch * 100 + o) * 50 + c];
        else if (c == 50) v = TSCL * b3[ch * 100 + o];
        else              v = 0.0f;
    }
    g_Wall[i] = v;
}

// ---------------- K1: per-pair MLP, f32x2 split-accumulator ----------------
__global__ __launch_bounds__(128, 4)
void k1_mlp(const float* __restrict__ coords, const int* __restrict__ types) {
    __shared__ __align__(16) float sw[CHW];

    const int tid  = threadIdx.x;
    const int wid  = tid >> 5;
    const int lane = tid & 31;

    int slot0 = g_plan[blockIdx.x * 4];
    if (slot0 < 0) return;                 // fully-padding block (uniform exit)

    {   // block channel from first slot (blocks are channel-pure)
        int u0 = slot0 >> 1;
        int n0 = u0 / NK, k0 = u0 % NK;
        int j0 = k0 + (k0 >= n0 ? 1 : 0);
        int ch = types[n0] * NTYPE + types[j0];
        const float4* src = (const float4*)(g_Wall + ch * CHW);
        float4* dst = (float4*)sw;
        for (int i = tid; i < CHW / 4; i += 128) dst[i] = src[i];
    }
    __syncthreads();

    int slot = g_plan[blockIdx.x * 4 + wid];
    if (slot < 0) return;                  // padding warp (after the only sync)

    const int u = slot >> 1;
    const int n = u / NK;
    const int k = u % NK;
    const int j = k + (k >= n ? 1 : 0);
    const int b = lane + ((slot & 1) << 5);

    const float* cb = coords + (size_t)b * NCAT * 3;
    float rx = cb[n * 3 + 0] - cb[j * 3 + 0];
    float ry = cb[n * 3 + 1] - cb[j * 3 + 1];
    float rz = cb[n * 3 + 2] - cb[j * 3 + 2];
    float d  = sqrtf(rx * rx + ry * ry + rz * rz);
    float x  = 1.0f / fmaxf(d, 1e-12f);

    // ---- layer 1: 1 -> 25, f32x2 pairs; pad slot carries 1.0 for bias-fold ----
    unsigned long long y1p[14];
#pragma unroll
    for (int q = 0; q < 12; q++) {
        float v0 = tanhS(fmaf(sw[2 * q],     x, sw[25 + 2 * q]));
        float v1 = tanhS(fmaf(sw[2 * q + 1], x, sw[25 + 2 * q + 1]));
        y1p[q] = pk2(v0, v1);
    }
    y1p[12] = pk2(tanhS(fmaf(sw[24], x, sw[49])), 1.0f);  // hi=1.0 -> bias col 25
    y1p[13] = pk2(0.0f, 0.0f);

    // ---- layer 2: 25 -> 50 (+ concat residual); bias comes via pad col ----
    unsigned long long y2p[26];
#pragma unroll
    for (int o = 0; o < 50; o += 2) {
        const float4* r0 = (const float4*)(sw + 200 + o * 28);
        const float4* r1 = (const float4*)(sw + 200 + (o + 1) * 28);
        unsigned long long a0 = pk2(0.0f, 0.0f), a1 = pk2(0.0f, 0.0f);
#pragma unroll
        for (int q = 0; q < 7; q++) {
            float4 w0 = r0[q], w1 = r1[q];
            a0 = fma2w(w0.x, w0.y, y1p[2 * q], a0);
            a0 = fma2w(w0.z, w0.w, y1p[2 * q + 1], a0);
            a1 = fma2w(w1.x, w1.y, y1p[2 * q], a1);
            a1 = fma2w(w1.z, w1.w, y1p[2 * q + 1], a1);
        }
        float l0, h0, l1, h1, rl, rh;
        unp2(a0, l0, h0);
        unp2(a1, l1, h1);
        int i0 = (o < 25) ? o : o - 25;
        int i1 = (o + 1 < 25) ? o + 1 : o - 24;
        float res0, res1;
        unp2(y1p[i0 >> 1], rl, rh);
        res0 = (i0 & 1) ? rh : rl;
        unp2(y1p[i1 >> 1], rl, rh);
        res1 = (i1 & 1) ? rh : rl;
        float v0 = tanhS(l0 + h0) + res0;
        float v1 = tanhS(l1 + h1) + res1;
        y2p[o / 2] = pk2(v0, v1);
    }
    y2p[25] = pk2(1.0f, 0.0f);            // lo=1.0 -> bias col 50

    // ---- layer 3: 50 -> 100 (+ concat residual), write fp16 ----
    __half* op = g_out + (((size_t)b * NCAT + n) * NK + k) * 100;
#pragma unroll
    for (int o = 0; o < 100; o += 4) {
        const float4* r0 = (const float4*)(sw + 1600 + (o + 0) * 52);
        const float4* r1 = (const float4*)(sw + 1600 + (o + 1) * 52);
        const float4* r2 = (const float4*)(sw + 1600 + (o + 2) * 52);
        const float4* r3 = (const float4*)(sw + 1600 + (o + 3) * 52);
        unsigned long long a0 = pk2(0.0f, 0.0f), a1 = a0, a2 = a0, a3 = a0;
#pragma unroll
        for (int q = 0; q < 13; q++) {
            unsigned long long xa = y2p[2 * q], xb = y2p[2 * q + 1];
            float4 w0 = r0[q];
            a0 = fma2w(w0.x, w0.y, xa, a0);
            a0 = fma2w(w0.z, w0.w, xb, a0);
            float4 w1 = r1[q];
            a1 = fma2w(w1.x, w1.y, xa, a1);
            a1 = fma2w(w1.z, w1.w, xb, a1);
            float4 w2 = r2[q];
            a2 = fma2w(w2.x, w2.y, xa, a2);
            a2 = fma2w(w2.z, w2.w, xb, a2);
            float4 w3 = r3[q];
            a3 = fma2w(w3.x, w3.y, xa, a3);
            a3 = fma2w(w3.z, w3.w, xb, a3);
        }
        float vx, vy, vz, vw;
        float lo, hi, rl, rh;
        {
            int ib = ((o + 0) < 50) ? (o + 0) : (o + 0 - 50);
            unp2(a0, lo, hi);
            unp2(y2p[ib >> 1], rl, rh);
            vx = tanhS(lo + hi) + ((ib & 1) ? rh : rl);
        }
        {
            int ib = ((o + 1) < 50) ? (o + 1) : (o + 1 - 50);
            unp2(a1, lo, hi);
            unp2(y2p[ib >> 1], rl, rh);
            vy = tanhS(lo + hi) + ((ib & 1) ? rh : rl);
        }
        {
            int ib = ((o + 2) < 50) ? (o + 2) : (o + 2 - 50);
            unp2(a2, lo, hi);
            unp2(y2p[ib >> 1], rl, rh);
            vz = tanhS(lo + hi) + ((ib & 1) ? rh : rl);
        }
        {
            int ib = ((o + 3) < 50) ? (o + 3) : (o + 3 - 50);
            unp2(a3, lo, hi);
            unp2(y2p[ib >> 1], rl, rh);
            vw = tanhS(lo + hi) + ((ib & 1) ? rh : rl);
        }
        __half2 h0 = __floats2half2_rn(vx, vy);
        __half2 h1 = __floats2half2_rn(vz, vw);
        uint2 st;
        st.x = *(unsigned int*)&h0;
        st.y = *(unsigned int*)&h1;
        *(uint2*)(op + o) = st;
    }
}

// ---------------- K2: contractions per (b, n) ----------------
__global__ __launch_bounds__(128)
void k2_contract(const float* __restrict__ coords, float* __restrict__ outp) {
    __shared__ float cs[NCAT * 3];
    __shared__ float t2s[NK * 4];
    __shared__ float t1s[12];
    __shared__ float red[48];
    __shared__ float part[4 * 25 * 16];   // per-warp phase-3 partials

    const int n   = blockIdx.x;
    const int b   = blockIdx.y;
    const int tid = threadIdx.x;
    const int warp = tid >> 5, lane = tid & 31;

    for (int i = tid; i < NCAT * 3; i += 128)
        cs[i] = coords[(size_t)b * NCAT * 3 + i];
    __syncthreads();

    const __half* obase = g_out + (((size_t)b * NCAT + n) * NK) * 100;

    float p[12];
#pragma unroll
    for (int i = 0; i < 12; i++) p[i] = 0.0f;
    float ax = 0.0f, ay = 0.0f, az = 0.0f;
    const int k = tid;

    if (k < NK) {
        int j = k + (k >= n ? 1 : 0);
        float rx = cs[n * 3 + 0] - cs[j * 3 + 0];
        float ry = cs[n * 3 + 1] - cs[j * 3 + 1];
        float rz = cs[n * 3 + 2] - cs[j * 3 + 2];
        float d  = sqrtf(rx * rx + ry * ry + rz * rz);
        float dinv = 1.0f / fmaxf(d, 1e-12f);
        float s = dinv * dinv;
        ax = rx * s; ay = ry * s; az = rz * s;

        __half2 p01 = *(const __half2*)(obase + (size_t)k * 100);
        __half2 p23 = *(const __half2*)(obase + (size_t)k * 100 + 2);
        float2 f01 = __half22float2(p01);
        float2 f23 = __half22float2(p23);
        p[0] = ax * f01.x; p[1] = ax * f01.y; p[2]  = ax * f23.x; p[3]  = ax * f23.y;
        p[4] = ay * f01.x; p[5] = ay * f01.y; p[6]  = ay * f23.x; p[7]  = ay * f23.y;
        p[8] = az * f01.x; p[9] = az * f01.y; p[10] = az * f23.x; p[11] = az * f23.y;
    }

#pragma unroll
    for (int i = 0; i < 12; i++) {
#pragma unroll
        for (int sh = 16; sh > 0; sh >>= 1)
            p[i] += __shfl_xor_sync(0xffffffffu, p[i], sh);
    }
    if (lane == 0) {
#pragma unroll
        for (int i = 0; i < 12; i++) red[warp * 12 + i] = p[i];
    }
    __syncthreads();
    if (tid < 12)
        t1s[tid] = red[tid] + red[12 + tid] + red[24 + tid] + red[36 + tid];
    __syncthreads();

    if (k < NK) {
        float4 t2;
        t2.x = ax * t1s[0] + ay * t1s[4] + az * t1s[8];
        t2.y = ax * t1s[1] + ay * t1s[5] + az * t1s[9];
        t2.z = ax * t1s[2] + ay * t1s[6] + az * t1s[10];
        t2.w = ax * t1s[3] + ay * t1s[7] + az * t1s[11];
        *(float4*)(t2s + k * 4) = t2;
    }
    __syncthreads();

    // ---- phase 3: res[g][f] = sum_k out[k][g] * t2[k][f] ----
    // warp w handles kk = w, w+4, ...; lanes 0..24 each own a g-quad (4 g's).
    float acc[16];
#pragma unroll
    for (int i = 0; i < 16; i++) acc[i] = 0.0f;

    if (lane < 25) {
        for (int kk = warp; kk < NK; kk += 4) {
            uint2 pr = *(const uint2*)(obase + (size_t)kk * 100 + lane * 4);
            __half2 h01 = *(__half2*)&pr.x;
            __half2 h23 = *(__half2*)&pr.y;
            float2 f01 = __half22float2(h01);
            float2 f23 = __half22float2(h23);
            float4 t = *(const float4*)(t2s + kk * 4);
            acc[0]  = fmaf(f01.x, t.x, acc[0]);
            acc[1]  = fmaf(f01.x, t.y, acc[1]);
            acc[2]  = fmaf(f01.x, t.z, acc[2]);
            acc[3]  = fmaf(f01.x, t.w, acc[3]);
            acc[4]  = fmaf(f01.y, t.x, acc[4]);
            acc[5]  = fmaf(f01.y, t.y, acc[5]);
            acc[6]  = fmaf(f01.y, t.z, acc[6]);
            acc[7]  = fmaf(f01.y, t.w, acc[7]);
            acc[8]  = fmaf(f23.x, t.x, acc[8]);
            acc[9]  = fmaf(f23.x, t.y, acc[9]);
            acc[10] = fmaf(f23.x, t.z, acc[10]);
            acc[11] = fmaf(f23.x, t.w, acc[11]);
            acc[12] = fmaf(f23.y, t.x, acc[12]);
            acc[13] = fmaf(f23.y, t.y, acc[13]);
            acc[14] = fmaf(f23.y, t.z, acc[14]);
            acc[15] = fmaf(f23.y, t.w, acc[15]);
        }
#pragma unroll
        for (int i = 0; i < 16; i++)
            part[(warp * 25 + lane) * 16 + i] = acc[i];
    }
    __syncthreads();

    if (tid < 100) {
        const int quad = tid >> 2, go = tid & 3;
        float4 r;
        r.x = r.y = r.z = r.w = 0.0f;
#pragma unroll
        for (int w = 0; w < 4; w++) {
            const float* pp = part + ((w * 25 + quad) * 16) + go * 4;
            r.x += pp[0];
            r.y += pp[1];
            r.z += pp[2];
            r.w += pp[3];
        }
        *(float4*)(outp + ((size_t)(b * NCAT + n)) * 400 + tid * 4) = r;
    }
}

extern "C" void kernel_launch(void* const* d_in, const int* in_sizes, int n_in,
                              void* d_out, int out_size) {
    const float* coords     = (const float*)d_in[0];
    const int*   atom_types = (const int*)d_in[1];
    const float* W1 = (const float*)d_in[2];
    const float* b1 = (const float*)d_in[3];
    const float* W2 = (const float*)d_in[4];
    const float* b2 = (const float*)d_in[5];
    const float* W3 = (const float*)d_in[6];
    const float* b3 = (const float*)d_in[7];
    float* outp = (float*)d_out;

    const int pack_blocks = (NCH * CHW + 255) / 256;       // 957
    prep_all<<<pack_blocks + 1, 256>>>(W1, b1, W2, b2, W3, b3, atom_types);
    k1_mlp<<<NBLK1, 128>>>(coords, atom_types);
    k2_contract<<<dim3(NCAT, NBATCH), 128>>>(coords, outp);
}

// round 9
// speedup vs baseline: 1.5495x; 1.5495x over previous
#include <cuda_runtime.h>
#include <cuda_fp16.h>
#include <math.h>

#define NBATCH 64
#define NCAT   128
#define NK     127
#define NTYPE  6
#define NCH    36
#define NUNIT  (NCAT * NK)       // 16256 (n,j) units
#define NSLOT  (NUNIT * 2)       // 32512 warp-slots (2 batch halves per unit)
#define NPLAN  (NSLOT + NCH * 4) // padded plan capacity
#define NBLK1  (NPLAN / 4)       // K1 blocks (4 warp-slots each)

// per-channel packed weight block layout (floats):
// [0,25)=W1  [25,50)=b1  [50,100)=b2  [100,200)=b3
// [200,1600)=W2 rows padded to 28   [1600,6800)=W3 rows padded to 52
#define CHW 6800

__device__ float  g_Wall[NCH * CHW];
__device__ int    g_plan[NPLAN];
__device__ __half g_out[(size_t)NBATCH * NCAT * NK * 100];  // MLP outputs (fp16)

// ---------------- f32x2 helpers ----------------
__device__ __forceinline__ unsigned long long pk2(float lo, float hi) {
    unsigned long long r;
    asm("mov.b64 %0, {%1, %2};" : "=l"(r) : "f"(lo), "f"(hi));
    return r;
}
__device__ __forceinline__ void unp2(unsigned long long v, float& lo, float& hi) {
    asm("mov.b64 {%0, %1}, %2;" : "=f"(lo), "=f"(hi) : "l"(v));
}
__device__ __forceinline__ unsigned long long fma2w(float wlo, float whi,
                                                    unsigned long long x,
                                                    unsigned long long acc) {
    unsigned long long w = pk2(wlo, whi);
    unsigned long long r;
    asm("fma.rn.f32x2 %0, %1, %2, %3;" : "=l"(r) : "l"(w), "l"(x), "l"(acc));
    return r;
}
// 5-op accurate tanh: 1 - 2*rcp(2^(2*log2e*v) + 1); exact at both limits.
__device__ __forceinline__ float tanh5(float v) {
    float e;
    asm("ex2.approx.ftz.f32 %0, %1;" : "=f"(e) : "f"(v * 2.885390082f));
    float r;
    asm("rcp.approx.ftz.f32 %0, %1;" : "=f"(r) : "f"(e + 1.0f));
    return fmaf(-2.0f, r, 1.0f);
}

// ---------------- prep: pack per-channel weight blocks ----------------
__global__ void prep_pack(const float* __restrict__ W1, const float* __restrict__ b1,
                          const float* __restrict__ W2, const float* __restrict__ b2,
                          const float* __restrict__ W3, const float* __restrict__ b3) {
    int i = blockIdx.x * blockDim.x + threadIdx.x;
    if (i >= NCH * CHW) return;
    int ch = i / CHW;
    int r  = i % CHW;
    float v;
    if (r < 25)        v = W1[ch * 25 + r];
    else if (r < 50)   v = b1[ch * 25 + (r - 25)];
    else if (r < 100)  v = b2[ch * 50 + (r - 50)];
    else if (r < 200)  v = b3[ch * 100 + (r - 100)];
    else if (r < 1600) {
        int rr = r - 200, o = rr / 28, c = rr % 28;
        v = (c < 25) ? W2[(ch * 50 + o) * 25 + c] : 0.0f;
    } else {
        int rr = r - 1600, o = rr / 52, c = rr % 52;
        v = (c < 50) ? W3[(ch * 100 + o) * 50 + c] : 0.0f;
    }
    g_Wall[i] = v;
}

// ---------------- prep: channel-pure warp-slot plan ----------------
__global__ void prep_plan(const int* __restrict__ types) {
    __shared__ int ts[NCAT];
    __shared__ int cnt[NCH];
    __shared__ int off[NCH];
    int t = threadIdx.x;

    for (int i = t; i < NPLAN; i += 256) g_plan[i] = -1;
    if (t < NCAT) ts[t] = types[t];
    if (t < NCH)  cnt[t] = 0;
    __syncthreads();

    for (int u = t; u < NUNIT; u += 256) {
        int n = u / NK, k = u % NK;
        int j = k + (k >= n ? 1 : 0);
        atomicAdd(&cnt[ts[n] * NTYPE + ts[j]], 2);
    }
    __syncthreads();
    if (t == 0) {
        int run = 0;
        for (int c = 0; c < NCH; c++) {
            off[c] = run;
            run += (cnt[c] + 3) & ~3;   // pad each channel to a multiple of 4 slots
        }
    }
    __syncthreads();
    for (int u = t; u < NUNIT; u += 256) {
        int n = u / NK, k = u % NK;
        int j = k + (k >= n ? 1 : 0);
        int c = ts[n] * NTYPE + ts[j];
        int pos = atomicAdd(&off[c], 2);
        g_plan[pos]     = u * 2;
        g_plan[pos + 1] = u * 2 + 1;
    }
}

// ---------------- K1: per-pair MLP, f32x2 split-accumulator (R6-proven) ----------------
__global__ __launch_bounds__(128, 4)
void k1_mlp(const float* __restrict__ coords, const int* __restrict__ types) {
    __shared__ __align__(16) float sw[CHW];

    const int tid  = threadIdx.x;
    const int wid  = tid >> 5;
    const int lane = tid & 31;

    int slot0 = g_plan[blockIdx.x * 4];
    if (slot0 < 0) return;                 // fully-padding block (uniform exit)

    {   // block channel from first slot (blocks are channel-pure)
        int u0 = slot0 >> 1;
        int n0 = u0 / NK, k0 = u0 % NK;
        int j0 = k0 + (k0 >= n0 ? 1 : 0);
        int ch = types[n0] * NTYPE + types[j0];
        const float4* src = (const float4*)(g_Wall + ch * CHW);
        float4* dst = (float4*)sw;
        for (int i = tid; i < CHW / 4; i += 128) dst[i] = src[i];
    }
    __syncthreads();

    int slot = g_plan[blockIdx.x * 4 + wid];
    if (slot < 0) return;                  // padding warp (after the only sync)

    const int u = slot >> 1;
    const int n = u / NK;
    const int k = u % NK;
    const int j = k + (k >= n ? 1 : 0);
    const int b = lane + ((slot & 1) << 5);

    const float* cb = coords + (size_t)b * NCAT * 3;
    float rx = cb[n * 3 + 0] - cb[j * 3 + 0];
    float ry = cb[n * 3 + 1] - cb[j * 3 + 1];
    float rz = cb[n * 3 + 2] - cb[j * 3 + 2];
    float d  = sqrtf(rx * rx + ry * ry + rz * rz);
    float x  = 1.0f / fmaxf(d, 1e-12f);

    // ---- layer 1: 1 -> 25, produced directly as f32x2 pairs ----
    unsigned long long y1p[14];
#pragma unroll
    for (int q = 0; q < 12; q++) {
        float v0 = tanh5(fmaf(sw[2 * q],     x, sw[25 + 2 * q]));
        float v1 = tanh5(fmaf(sw[2 * q + 1], x, sw[25 + 2 * q + 1]));
        y1p[q] = pk2(v0, v1);
    }
    y1p[12] = pk2(tanh5(fmaf(sw[24], x, sw[49])), 0.0f);
    y1p[13] = pk2(0.0f, 0.0f);

    // ---- layer 2: 25 -> 50 (+ concat residual) ----
    unsigned long long y2p[26];
#pragma unroll
    for (int o = 0; o < 50; o += 2) {
        const float4* r0 = (const float4*)(sw + 200 + o * 28);
        const float4* r1 = (const float4*)(sw + 200 + (o + 1) * 28);
        unsigned long long a0 = pk2(0.0f, 0.0f), a1 = pk2(0.0f, 0.0f);
#pragma unroll
        for (int q = 0; q < 7; q++) {
            float4 w0 = r0[q], w1 = r1[q];
            a0 = fma2w(w0.x, w0.y, y1p[2 * q], a0);
            a0 = fma2w(w0.z, w0.w, y1p[2 * q + 1], a0);
            a1 = fma2w(w1.x, w1.y, y1p[2 * q], a1);
            a1 = fma2w(w1.z, w1.w, y1p[2 * q + 1], a1);
        }
        float l0, h0, l1, h1, rl, rh;
        unp2(a0, l0, h0);
        unp2(a1, l1, h1);
        int i0 = (o < 25) ? o : o - 25;
        int i1 = (o + 1 < 25) ? o + 1 : o - 24;
        float res0, res1;
        unp2(y1p[i0 >> 1], rl, rh);
        res0 = (i0 & 1) ? rh : rl;
        unp2(y1p[i1 >> 1], rl, rh);
        res1 = (i1 & 1) ? rh : rl;
        float v0 = tanh5(l0 + h0 + sw[50 + o])     + res0;
        float v1 = tanh5(l1 + h1 + sw[50 + o + 1]) + res1;
        y2p[o / 2] = pk2(v0, v1);
    }
    y2p[25] = pk2(0.0f, 0.0f);

    // ---- layer 3: 50 -> 100 (+ concat residual), write fp16 to g_out ----
    __half* op = g_out + (((size_t)b * NCAT + n) * NK + k) * 100;
#pragma unroll
    for (int o = 0; o < 100; o += 4) {
        const float4* r0 = (const float4*)(sw + 1600 + (o + 0) * 52);
        const float4* r1 = (const float4*)(sw + 1600 + (o + 1) * 52);
        const float4* r2 = (const float4*)(sw + 1600 + (o + 2) * 52);
        const float4* r3 = (const float4*)(sw + 1600 + (o + 3) * 52);
        unsigned long long a0 = pk2(0.0f, 0.0f), a1 = a0, a2 = a0, a3 = a0;
#pragma unroll
        for (int q = 0; q < 13; q++) {
            unsigned long long xa = y2p[2 * q], xb = y2p[2 * q + 1];
            float4 w0 = r0[q];
            a0 = fma2w(w0.x, w0.y, xa, a0);
            a0 = fma2w(w0.z, w0.w, xb, a0);
            float4 w1 = r1[q];
            a1 = fma2w(w1.x, w1.y, xa, a1);
            a1 = fma2w(w1.z, w1.w, xb, a1);
            float4 w2 = r2[q];
            a2 = fma2w(w2.x, w2.y, xa, a2);
            a2 = fma2w(w2.z, w2.w, xb, a2);
            float4 w3 = r3[q];
            a3 = fma2w(w3.x, w3.y, xa, a3);
            a3 = fma2w(w3.z, w3.w, xb, a3);
        }
        float vx, vy, vz, vw;
        float lo, hi, rl, rh;
        {
            int ib = ((o + 0) < 50) ? (o + 0) : (o + 0 - 50);
            unp2(a0, lo, hi);
            unp2(y2p[ib >> 1], rl, rh);
            vx = tanh5(lo + hi + sw[100 + o + 0]) + ((ib & 1) ? rh : rl);
        }
        {
            int ib = ((o + 1) < 50) ? (o + 1) : (o + 1 - 50);
            unp2(a1, lo, hi);
            unp2(y2p[ib >> 1], rl, rh);
            vy = tanh5(lo + hi + sw[100 + o + 1]) + ((ib & 1) ? rh : rl);
        }
        {
            int ib = ((o + 2) < 50) ? (o + 2) : (o + 2 - 50);
            unp2(a2, lo, hi);
            unp2(y2p[ib >> 1], rl, rh);
            vz = tanh5(lo + hi + sw[100 + o + 2]) + ((ib & 1) ? rh : rl);
        }
        {
            int ib = ((o + 3) < 50) ? (o + 3) : (o + 3 - 50);
            unp2(a3, lo, hi);
            unp2(y2p[ib >> 1], rl, rh);
            vw = tanh5(lo + hi + sw[100 + o + 3]) + ((ib & 1) ? rh : rl);
        }
        __half2 h0 = __floats2half2_rn(vx, vy);
        __half2 h1 = __floats2half2_rn(vz, vw);
        uint2 st;
        st.x = *(unsigned int*)&h0;
        st.y = *(unsigned int*)&h1;
        *(uint2*)(op + o) = st;   // 8B aligned: rows are 200B, o%4==0
    }
}

// ---------------- K2: contractions per (b, n) ----------------
__global__ __launch_bounds__(128)
void k2_contract(const float* __restrict__ coords, float* __restrict__ outp) {
    __shared__ float cs[NCAT * 3];
    __shared__ float t2s[NK * 4];
    __shared__ float t1s[12];
    __shared__ float red[48];
    __shared__ float part[4 * 25 * 16];   // per-warp phase-3 partials

    const int n   = blockIdx.x;
    const int b   = blockIdx.y;
    const int tid = threadIdx.x;
    const int warp = tid >> 5, lane = tid & 31;

    for (int i = tid; i < NCAT * 3; i += 128)
        cs[i] = coords[(size_t)b * NCAT * 3 + i];
    __syncthreads();

    const __half* obase = g_out + (((size_t)b * NCAT + n) * NK) * 100;

    float p[12];
#pragma unroll
    for (int i = 0; i < 12; i++) p[i] = 0.0f;
    float ax = 0.0f, ay = 0.0f, az = 0.0f;
    const int k = tid;

    if (k < NK) {
        int j = k + (k >= n ? 1 : 0);
        float rx = cs[n * 3 + 0] - cs[j * 3 + 0];
        float ry = cs[n * 3 + 1] - cs[j * 3 + 1];
        float rz = cs[n * 3 + 2] - cs[j * 3 + 2];
        float d  = sqrtf(rx * rx + ry * ry + rz * rz);
        float dinv = 1.0f / fmaxf(d, 1e-12f);
        float s = dinv * dinv;
        ax = rx * s; ay = ry * s; az = rz * s;

        __half2 p01 = *(const __half2*)(obase + (size_t)k * 100);
        __half2 p23 = *(const __half2*)(obase + (size_t)k * 100 + 2);
        float2 f01 = __half22float2(p01);
        float2 f23 = __half22float2(p23);
        p[0] = ax * f01.x; p[1] = ax * f01.y; p[2]  = ax * f23.x; p[3]  = ax * f23.y;
        p[4] = ay * f01.x; p[5] = ay * f01.y; p[6]  = ay * f23.x; p[7]  = ay * f23.y;
        p[8] = az * f01.x; p[9] = az * f01.y; p[10] = az * f23.x; p[11] = az * f23.y;
    }

#pragma unroll
    for (int i = 0; i < 12; i++) {
#pragma unroll
        for (int sh = 16; sh > 0; sh >>= 1)
            p[i] += __shfl_xor_sync(0xffffffffu, p[i], sh);
    }
    if (lane == 0) {
#pragma unroll
        for (int i = 0; i < 12; i++) red[warp * 12 + i] = p[i];
    }
    __syncthreads();
    if (tid < 12)
        t1s[tid] = red[tid] + red[12 + tid] + red[24 + tid] + red[36 + tid];
    __syncthreads();

    if (k < NK) {
        float4 t2;
        t2.x = ax * t1s[0] + ay * t1s[4] + az * t1s[8];
        t2.y = ax * t1s[1] + ay * t1s[5] + az * t1s[9];
        t2.z = ax * t1s[2] + ay * t1s[6] + az * t1s[10];
        t2.w = ax * t1s[3] + ay * t1s[7] + az * t1s[11];
        *(float4*)(t2s + k * 4) = t2;
    }
    __syncthreads();

    // ---- phase 3: res[g][f] = sum_k out[k][g] * t2[k][f] ----
    // warp w handles kk = w, w+4, ...; lanes 0..24 each own a g-quad (4 g's).
    float acc[16];
#pragma unroll
    for (int i = 0; i < 16; i++) acc[i] = 0.0f;

    if (lane < 25) {
        for (int kk = warp; kk < NK; kk += 4) {
            uint2 pr = *(const uint2*)(obase + (size_t)kk * 100 + lane * 4);
            __half2 h01 = *(__half2*)&pr.x;
            __half2 h23 = *(__half2*)&pr.y;
            float2 f01 = __half22float2(h01);
            float2 f23 = __half22float2(h23);
            float4 t = *(const float4*)(t2s + kk * 4);
            acc[0]  = fmaf(f01.x, t.x, acc[0]);
            acc[1]  = fmaf(f01.x, t.y, acc[1]);
            acc[2]  = fmaf(f01.x, t.z, acc[2]);
            acc[3]  = fmaf(f01.x, t.w, acc[3]);
            acc[4]  = fmaf(f01.y, t.x, acc[4]);
            acc[5]  = fmaf(f01.y, t.y, acc[5]);
            acc[6]  = fmaf(f01.y, t.z, acc[6]);
            acc[7]  = fmaf(f01.y, t.w, acc[7]);
            acc[8]  = fmaf(f23.x, t.x, acc[8]);
            acc[9]  = fmaf(f23.x, t.y, acc[9]);
            acc[10] = fmaf(f23.x, t.z, acc[10]);
            acc[11] = fmaf(f23.x, t.w, acc[11]);
            acc[12] = fmaf(f23.y, t.x, acc[12]);
            acc[13] = fmaf(f23.y, t.y, acc[13]);
            acc[14] = fmaf(f23.y, t.z, acc[14]);
            acc[15] = fmaf(f23.y, t.w, acc[15]);
        }
#pragma unroll
        for (int i = 0; i < 16; i++)
            part[(warp * 25 + lane) * 16 + i] = acc[i];
    }
    __syncthreads();

    if (tid < 100) {
        const int quad = tid >> 2, go = tid & 3;
        float4 r;
        r.x = r.y = r.z = r.w = 0.0f;
#pragma unroll
        for (int w = 0; w < 4; w++) {
            const float* pp = part + ((w * 25 + quad) * 16) + go * 4;
            r.x += pp[0];
            r.y += pp[1];
            r.z += pp[2];
            r.w += pp[3];
        }
        *(float4*)(outp + ((size_t)(b * NCAT + n)) * 400 + tid * 4) = r;
    }
}

extern "C" void kernel_launch(void* const* d_in, const int* in_sizes, int n_in,
                              void* d_out, int out_size) {
    const float* coords     = (const float*)d_in[0];
    const int*   atom_types = (const int*)d_in[1];
    const float* W1 = (const float*)d_in[2];
    const float* b1 = (const float*)d_in[3];
    const float* W2 = (const float*)d_in[4];
    const float* b2 = (const float*)d_in[5];
    const float* W3 = (const float*)d_in[6];
    const float* b3 = (const float*)d_in[7];
    float* outp = (float*)d_out;

    prep_pack<<<(NCH * CHW + 255) / 256, 256>>>(W1, b1, W2, b2, W3, b3);
    prep_plan<<<1, 256>>>(atom_types);
    k1_mlp<<<NBLK1, 128>>>(coords, atom_types);
    k2_contract<<<dim3(NCAT, NBATCH), 128>>>(coords, outp);
}

// round 10
// speedup vs baseline: 1.6278x; 1.0505x over previous
#include <cuda_runtime.h>
#include <cuda_fp16.h>
#include <math.h>

#define NBATCH 64
#define NCAT   128
#define NK     127
#define NTYPE  6
#define NCH    36
#define NUNIT  (NCAT * NK)       // 16256 (n,j) units
#define NSLOT  (NUNIT * 2)       // 32512 warp-slots (2 batch halves per unit)
#define NPLAN  (NSLOT + NCH * 4) // padded plan capacity
#define NBLK1  (NPLAN / 4)       // K1 blocks (4 warp-slots each)

// per-channel packed weight block layout (floats):
// [0,25)=W1  [25,50)=b1  [50,100)=b2  [100,200)=b3
// [200,1600)=W2 rows padded to 28   [1600,6800)=W3 rows padded to 52
// ALL entries pre-scaled by TSCL = 2*log2(e) so tanh needs no input multiply.
#define CHW 6800
#define TSCL 2.885390081777927f

__device__ float  g_Wall[NCH * CHW];
__device__ int    g_plan[NPLAN];
__device__ __half g_out[(size_t)NBATCH * NCAT * NK * 100];  // MLP outputs (fp16)

// ---------------- f32x2 helpers ----------------
__device__ __forceinline__ unsigned long long pk2(float lo, float hi) {
    unsigned long long r;
    asm("mov.b64 %0, {%1, %2};" : "=l"(r) : "f"(lo), "f"(hi));
    return r;
}
__device__ __forceinline__ void unp2(unsigned long long v, float& lo, float& hi) {
    asm("mov.b64 {%0, %1}, %2;" : "=f"(lo), "=f"(hi) : "l"(v));
}
__device__ __forceinline__ unsigned long long fma2w(float wlo, float whi,
                                                    unsigned long long x,
                                                    unsigned long long acc) {
    unsigned long long w = pk2(wlo, whi);
    unsigned long long r;
    asm("fma.rn.f32x2 %0, %1, %2, %3;" : "=l"(r) : "l"(w), "l"(x), "l"(acc));
    return r;
}
// tanh on PRE-SCALED input s = 2*log2e*v : 1 - 2*rcp(2^s + 1). 4 ops.
__device__ __forceinline__ float tanhS(float s) {
    float e;
    asm("ex2.approx.ftz.f32 %0, %1;" : "=f"(e) : "f"(s));
    float r;
    asm("rcp.approx.ftz.f32 %0, %1;" : "=f"(r) : "f"(e + 1.0f));
    return fmaf(-2.0f, r, 1.0f);
}

// ---------------- prep: pack per-channel weight blocks (pre-scaled) ----------------
__global__ void prep_pack(const float* __restrict__ W1, const float* __restrict__ b1,
                          const float* __restrict__ W2, const float* __restrict__ b2,
                          const float* __restrict__ W3, const float* __restrict__ b3) {
    int i = blockIdx.x * blockDim.x + threadIdx.x;
    if (i >= NCH * CHW) return;
    int ch = i / CHW;
    int r  = i % CHW;
    float v;
    if (r < 25)        v = TSCL * W1[ch * 25 + r];
    else if (r < 50)   v = TSCL * b1[ch * 25 + (r - 25)];
    else if (r < 100)  v = TSCL * b2[ch * 50 + (r - 50)];
    else if (r < 200)  v = TSCL * b3[ch * 100 + (r - 100)];
    else if (r < 1600) {
        int rr = r - 200, o = rr / 28, c = rr % 28;
        v = (c < 25) ? TSCL * W2[(ch * 50 + o) * 25 + c] : 0.0f;
    } else {
        int rr = r - 1600, o = rr / 52, c = rr % 52;
        v = (c < 50) ? TSCL * W3[(ch * 100 + o) * 50 + c] : 0.0f;
    }
    g_Wall[i] = v;
}

// ---------------- prep: channel-pure warp-slot plan ----------------
__global__ void prep_plan(const int* __restrict__ types) {
    __shared__ int ts[NCAT];
    __shared__ int cnt[NCH];
    __shared__ int off[NCH];
    int t = threadIdx.x;

    for (int i = t; i < NPLAN; i += 256) g_plan[i] = -1;
    if (t < NCAT) ts[t] = types[t];
    if (t < NCH)  cnt[t] = 0;
    __syncthreads();

    for (int u = t; u < NUNIT; u += 256) {
        int n = u / NK, k = u % NK;
        int j = k + (k >= n ? 1 : 0);
        atomicAdd(&cnt[ts[n] * NTYPE + ts[j]], 2);
    }
    __syncthreads();
    if (t == 0) {
        int run = 0;
        for (int c = 0; c < NCH; c++) {
            off[c] = run;
            run += (cnt[c] + 3) & ~3;   // pad each channel to a multiple of 4 slots
        }
    }
    __syncthreads();
    for (int u = t; u < NUNIT; u += 256) {
        int n = u / NK, k = u % NK;
        int j = k + (k >= n ? 1 : 0);
        int c = ts[n] * NTYPE + ts[j];
        int pos = atomicAdd(&off[c], 2);
        g_plan[pos]     = u * 2;
        g_plan[pos + 1] = u * 2 + 1;
    }
}

// ---------------- K1: per-pair MLP, f32x2 split-accumulator ----------------
// Structure identical to the proven R6 kernel; only change: tanh5 -> tanhS
// (input multiply folded into pre-scaled weights). Bias adds kept as-is.
__global__ __launch_bounds__(128, 4)
void k1_mlp(const float* __restrict__ coords, const int* __restrict__ types) {
    __shared__ __align__(16) float sw[CHW];

    const int tid  = threadIdx.x;
    const int wid  = tid >> 5;
    const int lane = tid & 31;

    int slot0 = g_plan[blockIdx.x * 4];
    if (slot0 < 0) return;                 // fully-padding block (uniform exit)

    {   // block channel from first slot (blocks are channel-pure)
        int u0 = slot0 >> 1;
        int n0 = u0 / NK, k0 = u0 % NK;
        int j0 = k0 + (k0 >= n0 ? 1 : 0);
        int ch = types[n0] * NTYPE + types[j0];
        const float4* src = (const float4*)(g_Wall + ch * CHW);
        float4* dst = (float4*)sw;
        for (int i = tid; i < CHW / 4; i += 128) dst[i] = src[i];
    }
    __syncthreads();

    int slot = g_plan[blockIdx.x * 4 + wid];
    if (slot < 0) return;                  // padding warp (after the only sync)

    const int u = slot >> 1;
    const int n = u / NK;
    const int k = u % NK;
    const int j = k + (k >= n ? 1 : 0);
    const int b = lane + ((slot & 1) << 5);

    const float* cb = coords + (size_t)b * NCAT * 3;
    float rx = cb[n * 3 + 0] - cb[j * 3 + 0];
    float ry = cb[n * 3 + 1] - cb[j * 3 + 1];
    float rz = cb[n * 3 + 2] - cb[j * 3 + 2];
    float d  = sqrtf(rx * rx + ry * ry + rz * rz);
    float x  = 1.0f / fmaxf(d, 1e-12f);

    // ---- layer 1: 1 -> 25, produced directly as f32x2 pairs ----
    unsigned long long y1p[14];
#pragma unroll
    for (int q = 0; q < 12; q++) {
        float v0 = tanhS(fmaf(sw[2 * q],     x, sw[25 + 2 * q]));
        float v1 = tanhS(fmaf(sw[2 * q + 1], x, sw[25 + 2 * q + 1]));
        y1p[q] = pk2(v0, v1);
    }
    y1p[12] = pk2(tanhS(fmaf(sw[24], x, sw[49])), 0.0f);
    y1p[13] = pk2(0.0f, 0.0f);

    // ---- layer 2: 25 -> 50 (+ concat residual) ----
    unsigned long long y2p[26];
#pragma unroll
    for (int o = 0; o < 50; o += 2) {
        const float4* r0 = (const float4*)(sw + 200 + o * 28);
        const float4* r1 = (const float4*)(sw + 200 + (o + 1) * 28);
        unsigned long long a0 = pk2(0.0f, 0.0f), a1 = pk2(0.0f, 0.0f);
#pragma unroll
        for (int q = 0; q < 7; q++) {
            float4 w0 = r0[q], w1 = r1[q];
            a0 = fma2w(w0.x, w0.y, y1p[2 * q], a0);
            a0 = fma2w(w0.z, w0.w, y1p[2 * q + 1], a0);
            a1 = fma2w(w1.x, w1.y, y1p[2 * q], a1);
            a1 = fma2w(w1.z, w1.w, y1p[2 * q + 1], a1);
        }
        float l0, h0, l1, h1, rl, rh;
        unp2(a0, l0, h0);
        unp2(a1, l1, h1);
        int i0 = (o < 25) ? o : o - 25;
        int i1 = (o + 1 < 25) ? o + 1 : o - 24;
        float res0, res1;
        unp2(y1p[i0 >> 1], rl, rh);
        res0 = (i0 & 1) ? rh : rl;
        unp2(y1p[i1 >> 1], rl, rh);
        res1 = (i1 & 1) ? rh : rl;
        float v0 = tanhS(l0 + h0 + sw[50 + o])     + res0;
        float v1 = tanhS(l1 + h1 + sw[50 + o + 1]) + res1;
        y2p[o / 2] = pk2(v0, v1);
    }
    y2p[25] = pk2(0.0f, 0.0f);

    // ---- layer 3: 50 -> 100 (+ concat residual), write fp16 to g_out ----
    __half* op = g_out + (((size_t)b * NCAT + n) * NK + k) * 100;
#pragma unroll
    for (int o = 0; o < 100; o += 4) {
        const float4* r0 = (const float4*)(sw + 1600 + (o + 0) * 52);
        const float4* r1 = (const float4*)(sw + 1600 + (o + 1) * 52);
        const float4* r2 = (const float4*)(sw + 1600 + (o + 2) * 52);
        const float4* r3 = (const float4*)(sw + 1600 + (o + 3) * 52);
        unsigned long long a0 = pk2(0.0f, 0.0f), a1 = a0, a2 = a0, a3 = a0;
#pragma unroll
        for (int q = 0; q < 13; q++) {
            unsigned long long xa = y2p[2 * q], xb = y2p[2 * q + 1];
            float4 w0 = r0[q];
            a0 = fma2w(w0.x, w0.y, xa, a0);
            a0 = fma2w(w0.z, w0.w, xb, a0);
            float4 w1 = r1[q];
            a1 = fma2w(w1.x, w1.y, xa, a1);
            a1 = fma2w(w1.z, w1.w, xb, a1);
            float4 w2 = r2[q];
            a2 = fma2w(w2.x, w2.y, xa, a2);
            a2 = fma2w(w2.z, w2.w, xb, a2);
            float4 w3 = r3[q];
            a3 = fma2w(w3.x, w3.y, xa, a3);
            a3 = fma2w(w3.z, w3.w, xb, a3);
        }
        float vx, vy, vz, vw;
        float lo, hi, rl, rh;
        {
            int ib = ((o + 0) < 50) ? (o + 0) : (o + 0 - 50);
            unp2(a0, lo, hi);
            unp2(y2p[ib >> 1], rl, rh);
            vx = tanhS(lo + hi + sw[100 + o + 0]) + ((ib & 1) ? rh : rl);
        }
        {
            int ib = ((o + 1) < 50) ? (o + 1) : (o + 1 - 50);
            unp2(a1, lo, hi);
            unp2(y2p[ib >> 1], rl, rh);
            vy = tanhS(lo + hi + sw[100 + o + 1]) + ((ib & 1) ? rh : rl);
        }
        {
            int ib = ((o + 2) < 50) ? (o + 2) : (o + 2 - 50);
            unp2(a2, lo, hi);
            unp2(y2p[ib >> 1], rl, rh);
            vz = tanhS(lo + hi + sw[100 + o + 2]) + ((ib & 1) ? rh : rl);
        }
        {
            int ib = ((o + 3) < 50) ? (o + 3) : (o + 3 - 50);
            unp2(a3, lo, hi);
            unp2(y2p[ib >> 1], rl, rh);
            vw = tanhS(lo + hi + sw[100 + o + 3]) + ((ib & 1) ? rh : rl);
        }
        __half2 h0 = __floats2half2_rn(vx, vy);
        __half2 h1 = __floats2half2_rn(vz, vw);
        uint2 st;
        st.x = *(unsigned int*)&h0;
        st.y = *(unsigned int*)&h1;
        *(uint2*)(op + o) = st;   // 8B aligned: rows are 200B, o%4==0
    }
}

// ---------------- K2: res = M * M[0:4]^T  with M[g][a] = sum_k out[k][g]*a[k][a] ----
// Identity: res[g][f] = sum_k out[k][g] * t2[k][f]
//                     = sum_a (sum_k out[k][g] a[k][a]) * t1[a][f] = sum_a M[g][a]*M[f][a]
// -> single pass over `out`, no t1/t2 stages.
__global__ __launch_bounds__(128)
void k2_contract(const float* __restrict__ coords, float* __restrict__ outp) {
    __shared__ float cs[NCAT * 3];
    __shared__ float as_[NK * 3];          // loc_env_a per k
    __shared__ float Mpart[4][25][12];     // per-warp partial M (quad of g x 3 axes)
    __shared__ float Ms[100 * 3];          // final M

    const int n   = blockIdx.x;
    const int b   = blockIdx.y;
    const int tid = threadIdx.x;
    const int warp = tid >> 5, lane = tid & 31;

    for (int i = tid; i < NCAT * 3; i += 128)
        cs[i] = coords[(size_t)b * NCAT * 3 + i];
    __syncthreads();

    if (tid < NK) {
        int k = tid;
        int j = k + (k >= n ? 1 : 0);
        float rx = cs[n * 3 + 0] - cs[j * 3 + 0];
        float ry = cs[n * 3 + 1] - cs[j * 3 + 1];
        float rz = cs[n * 3 + 2] - cs[j * 3 + 2];
        float d  = sqrtf(rx * rx + ry * ry + rz * rz);
        float dinv = 1.0f / fmaxf(d, 1e-12f);
        float s = dinv * dinv;
        as_[k * 3 + 0] = rx * s;
        as_[k * 3 + 1] = ry * s;
        as_[k * 3 + 2] = rz * s;
    }
    __syncthreads();

    const __half* obase = g_out + (((size_t)b * NCAT + n) * NK) * 100;

    // M accumulation: warp w strides kk, lanes 0..24 own a g-quad.
    float acc[12];
#pragma unroll
    for (int i = 0; i < 12; i++) acc[i] = 0.0f;

    if (lane < 25) {
        for (int kk = warp; kk < NK; kk += 4) {
            uint2 pr = *(const uint2*)(obase + (size_t)kk * 100 + lane * 4);
            __half2 h01 = *(__half2*)&pr.x;
            __half2 h23 = *(__half2*)&pr.y;
            float2 f01 = __half22float2(h01);
            float2 f23 = __half22float2(h23);
            float a0 = as_[kk * 3 + 0];
            float a1 = as_[kk * 3 + 1];
            float a2 = as_[kk * 3 + 2];
            acc[0]  = fmaf(f01.x, a0, acc[0]);
            acc[1]  = fmaf(f01.x, a1, acc[1]);
            acc[2]  = fmaf(f01.x, a2, acc[2]);
            acc[3]  = fmaf(f01.y, a0, acc[3]);
            acc[4]  = fmaf(f01.y, a1, acc[4]);
            acc[5]  = fmaf(f01.y, a2, acc[5]);
            acc[6]  = fmaf(f23.x, a0, acc[6]);
            acc[7]  = fmaf(f23.x, a1, acc[7]);
            acc[8]  = fmaf(f23.x, a2, acc[8]);
            acc[9]  = fmaf(f23.y, a0, acc[9]);
            acc[10] = fmaf(f23.y, a1, acc[10]);
            acc[11] = fmaf(f23.y, a2, acc[11]);
        }
#pragma unroll
        for (int i = 0; i < 12; i++) Mpart[warp][lane][i] = acc[i];
    }
    __syncthreads();

    float m0 = 0.0f, m1 = 0.0f, m2 = 0.0f;
    if (tid < 100) {
        const int quad = tid >> 2, e = tid & 3;
#pragma unroll
        for (int w = 0; w < 4; w++) {
            m0 += Mpart[w][quad][e * 3 + 0];
            m1 += Mpart[w][quad][e * 3 + 1];
            m2 += Mpart[w][quad][e * 3 + 2];
        }
        Ms[tid * 3 + 0] = m0;
        Ms[tid * 3 + 1] = m1;
        Ms[tid * 3 + 2] = m2;
    }
    __syncthreads();

    if (tid < 100) {
        float4 r;
        r.x = m0 * Ms[0]  + m1 * Ms[1]  + m2 * Ms[2];
        r.y = m0 * Ms[3]  + m1 * Ms[4]  + m2 * Ms[5];
        r.z = m0 * Ms[6]  + m1 * Ms[7]  + m2 * Ms[8];
        r.w = m0 * Ms[9]  + m1 * Ms[10] + m2 * Ms[11];
        *(float4*)(outp + ((size_t)(b * NCAT + n)) * 400 + tid * 4) = r;
    }
}

extern "C" void kernel_launch(void* const* d_in, const int* in_sizes, int n_in,
                              void* d_out, int out_size) {
    const float* coords     = (const float*)d_in[0];
    const int*   atom_types = (const int*)d_in[1];
    const float* W1 = (const float*)d_in[2];
    const float* b1 = (const float*)d_in[3];
    const float* W2 = (const float*)d_in[4];
    const float* b2 = (const float*)d_in[5];
    const float* W3 = (const float*)d_in[6];
    const float* b3 = (const float*)d_in[7];
    float* outp = (float*)d_out;

    prep_pack<<<(NCH * CHW + 255) / 256, 256>>>(W1, b1, W2, b2, W3, b3);
    prep_plan<<<1, 256>>>(atom_types);
    k1_mlp<<<NBLK1, 128>>>(coords, atom_types);
    k2_contract<<<dim3(NCAT, NBATCH), 128>>>(coords, outp);
}

// round 11
// speedup vs baseline: 4.0816x; 2.5075x over previous
#include <cuda_runtime.h>
#include <cuda_fp16.h>
#include <math.h>

#define NBATCH 64
#define NCAT   128
#define NK     127
#define NTYPE  6
#define NCH    36
#define NUNIT  (NCAT * NK)       // 16256 (n,j) units
#define NSLOT  (NUNIT * 2)       // 32512 warp-slots (2 batch halves per unit)
#define NPLAN  (NSLOT + NCH * 4) // padded plan capacity (32656)
#define NBLK1  (NPLAN / 4)       // K1 blocks (8164)

#define TSCL 2.885390081777927f  // 2*log2(e), folded into all weights/biases

// smem strides (halfs) — chosen conflict-free for fragment loads
#define SA  40   // A1 (y1) rows: 32 cols used
#define SW2 40   // W2h rows: 32 cols used
#define SW3 72   // W3h rows: 64 cols used
#define SY  72   // Y2 rows: 64 cols used

// fp16 weight blocks, per channel:
//  g_W1  [64]  fp32: [0,25)=TSCL*W1, [25,50)=TSCL*b1
//  g_Wh2 [56*40] half: rows o<50: k<25 = TSCL*W2[o][k], k==25 = TSCL*b2[o], else 0
//  g_Wh3 [104*72] half: rows o<100: k<50 = TSCL*W3[o][k], k==50 = TSCL*b3[o], else 0
__device__ float  g_W1[NCH * 64];
__device__ __half g_Wh2[NCH * 56 * SW2];
__device__ __half g_Wh3[NCH * 104 * SW3];
__device__ int    g_plan[NPLAN];
__device__ int    g_sinv[NSLOT];                       // slot value -> plan position
__device__ __half g_out[(size_t)NPLAN * 32 * 100];     // sample-major MLP outputs

// tanh on PRE-SCALED input s = 2*log2e*v : 1 - 2*rcp(2^s + 1)
__device__ __forceinline__ float tanhS(float s) {
    float e;
    asm("ex2.approx.ftz.f32 %0, %1;" : "=f"(e) : "f"(s));
    float r;
    asm("rcp.approx.ftz.f32 %0, %1;" : "=f"(r) : "f"(e + 1.0f));
    return fmaf(-2.0f, r, 1.0f);
}

__device__ __forceinline__ void mma16816(float c[4], const unsigned a[4],
                                         unsigned b0, unsigned b1) {
    asm volatile(
        "mma.sync.aligned.m16n8k16.row.col.f32.f16.f16.f32 "
        "{%0,%1,%2,%3}, {%4,%5,%6,%7}, {%8,%9}, {%0,%1,%2,%3};"
        : "+f"(c[0]), "+f"(c[1]), "+f"(c[2]), "+f"(c[3])
        : "r"(a[0]), "r"(a[1]), "r"(a[2]), "r"(a[3]), "r"(b0), "r"(b1));
}

// ---------------- prep: fp16 weight packs (pre-scaled, bias-folded) ----------------
__global__ void prep_packh(const float* __restrict__ W1, const float* __restrict__ b1,
                           const float* __restrict__ W2, const float* __restrict__ b2,
                           const float* __restrict__ W3, const float* __restrict__ b3) {
    const int S1 = NCH * 64;
    const int S2 = NCH * 56 * SW2;
    const int S3 = NCH * 104 * SW3;
    for (int i = blockIdx.x * blockDim.x + threadIdx.x; i < S1 + S2 + S3;
         i += gridDim.x * blockDim.x) {
        if (i < S1) {
            int ch = i / 64, r = i % 64;
            float v = 0.0f;
            if (r < 25)      v = TSCL * W1[ch * 25 + r];
            else if (r < 50) v = TSCL * b1[ch * 25 + (r - 25)];
            g_W1[i] = v;
        } else if (i < S1 + S2) {
            int ii = i - S1;
            int ch = ii / (56 * SW2), rr = ii % (56 * SW2);
            int o = rr / SW2, k = rr % SW2;
            float v = 0.0f;
            if (o < 50) {
                if (k < 25)       v = TSCL * W2[(ch * 50 + o) * 25 + k];
                else if (k == 25) v = TSCL * b2[ch * 50 + o];
            }
            g_Wh2[ii] = __float2half(v);
        } else {
            int ii = i - S1 - S2;
            int ch = ii / (104 * SW3), rr = ii % (104 * SW3);
            int o = rr / SW3, k = rr % SW3;
            float v = 0.0f;
            if (o < 100) {
                if (k < 50)       v = TSCL * W3[(ch * 100 + o) * 50 + k];
                else if (k == 50) v = TSCL * b3[ch * 100 + o];
            }
            g_Wh3[ii] = __float2half(v);
        }
    }
}

// ---------------- prep: channel-pure warp-slot plan + inverse map ----------------
__global__ void prep_plan(const int* __restrict__ types) {
    __shared__ int ts[NCAT];
    __shared__ int cnt[NCH];
    __shared__ int off[NCH];
    int t = threadIdx.x;

    for (int i = t; i < NPLAN; i += 256) g_plan[i] = -1;
    if (t < NCAT) ts[t] = types[t];
    if (t < NCH)  cnt[t] = 0;
    __syncthreads();

    for (int u = t; u < NUNIT; u += 256) {
        int n = u / NK, k = u % NK;
        int j = k + (k >= n ? 1 : 0);
        atomicAdd(&cnt[ts[n] * NTYPE + ts[j]], 2);
    }
    __syncthreads();
    if (t == 0) {
        int run = 0;
        for (int c = 0; c < NCH; c++) {
            off[c] = run;
            run += (cnt[c] + 3) & ~3;
        }
    }
    __syncthreads();
    for (int u = t; u < NUNIT; u += 256) {
        int n = u / NK, k = u % NK;
        int j = k + (k >= n ? 1 : 0);
        int c = ts[n] * NTYPE + ts[j];
        int pos = atomicAdd(&off[c], 2);
        g_plan[pos]     = u * 2;
        g_plan[pos + 1] = u * 2 + 1;
        g_sinv[u * 2]     = pos;
        g_sinv[u * 2 + 1] = pos + 1;
    }
}

// ---------------- K1: channel-pure MLP via m16n8k16 tensor GEMMs ----------------
__global__ __launch_bounds__(128, 4)
void k1_mlp(const float* __restrict__ coords, const int* __restrict__ types) {
    __shared__ __align__(16) float  W1f[64];
    __shared__ __align__(16) __half A1[128 * SA];
    __shared__ __align__(16) __half W2h[56 * SW2];
    __shared__ __align__(16) __half W3h[104 * SW3];
    __shared__ __align__(16) __half Y2[128 * SY];

    const int tid  = threadIdx.x;
    const int wid  = tid >> 5;
    const int lane = tid & 31;
    const int gid  = lane >> 2;        // fragment row group
    const int qc   = (lane & 3) * 2;   // fragment col pair

    const int slot0 = g_plan[blockIdx.x * 4];
    if (slot0 < 0) return;             // fully-padding block

    int ch;
    {
        int u0 = slot0 >> 1;
        int n0 = u0 / NK, k0 = u0 % NK;
        int j0 = k0 + (k0 >= n0 ? 1 : 0);
        ch = types[n0] * NTYPE + types[j0];
    }

    // stage per-channel weights
    if (tid < 16) ((uint4*)W1f)[tid] = ((const uint4*)(g_W1 + ch * 64))[tid];
    {
        const uint4* s2 = (const uint4*)(g_Wh2 + (size_t)ch * 56 * SW2);
        for (int i = tid; i < 56 * SW2 / 8; i += 128) ((uint4*)W2h)[i] = s2[i];
        const uint4* s3 = (const uint4*)(g_Wh3 + (size_t)ch * 104 * SW3);
        for (int i = tid; i < 104 * SW3 / 8; i += 128) ((uint4*)W3h)[i] = s3[i];
    }

    int slot = g_plan[blockIdx.x * 4 + wid];
    if (slot < 0) slot = slot0;        // padding warp: safe same-channel fallback
    const int u  = slot >> 1;
    const int un = u / NK;
    const int uk = u % NK;
    const int uj = uk + (uk >= un ? 1 : 0);
    const int b  = lane + ((slot & 1) << 5);

    // per-sample input x
    const float* cb = coords + (size_t)b * NCAT * 3;
    float rx = cb[un * 3 + 0] - cb[uj * 3 + 0];
    float ry = cb[un * 3 + 1] - cb[uj * 3 + 1];
    float rz = cb[un * 3 + 2] - cb[uj * 3 + 2];
    float d  = sqrtf(rx * rx + ry * ry + rz * rz);
    float x  = 1.0f / fmaxf(d, 1e-12f);

    __syncthreads();   // weights staged

    // ---- layer 1 (fp32, exact) -> A1 fp16 rows; col 25 = 1.0 (bias input) ----
    {
        __half* row = A1 + tid * SA;
#pragma unroll
        for (int q = 0; q < 12; q++) {
            float v0 = tanhS(fmaf(W1f[2 * q],     x, W1f[25 + 2 * q]));
            float v1 = tanhS(fmaf(W1f[2 * q + 1], x, W1f[25 + 2 * q + 1]));
            *(__half2*)(row + 2 * q) = __floats2half2_rn(v0, v1);
        }
        float v24 = tanhS(fmaf(W1f[24], x, W1f[49]));
        *(__half2*)(row + 24) = __floats2half2_rn(v24, 1.0f);
        *(__half2*)(row + 26) = __floats2half2_rn(0.0f, 0.0f);
        *(__half2*)(row + 28) = __floats2half2_rn(0.0f, 0.0f);
        *(__half2*)(row + 30) = __floats2half2_rn(0.0f, 0.0f);
        // Y2 pad: col 50 = 1.0 (bias), cols 51..63 = 0
        __half* yrow = Y2 + tid * SY;
        *(__half2*)(yrow + 50) = __floats2half2_rn(1.0f, 0.0f);
#pragma unroll
        for (int c = 52; c < 64; c += 2)
            *(__half2*)(yrow + c) = __floats2half2_rn(0.0f, 0.0f);
    }
    __syncthreads();

    const int RB = wid * 32;   // this warp's 32 sample rows

    // ---- layer 2 GEMM: Y2[128x50] = tanh(A1[128x26] * W2^T) + concat(y1,y1) ----
    {
        unsigned aF[2][2][4];
#pragma unroll
        for (int mt = 0; mt < 2; mt++)
#pragma unroll
            for (int kt = 0; kt < 2; kt++) {
                const __half* base = A1 + (RB + mt * 16 + gid) * SA + kt * 16 + qc;
                aF[mt][kt][0] = *(const unsigned*)(base);
                aF[mt][kt][1] = *(const unsigned*)(base + 8 * SA);
                aF[mt][kt][2] = *(const unsigned*)(base + 8);
                aF[mt][kt][3] = *(const unsigned*)(base + 8 * SA + 8);
            }
#pragma unroll
        for (int nt = 0; nt < 7; nt++) {
            float c0[4] = {0.f, 0.f, 0.f, 0.f};
            float c1[4] = {0.f, 0.f, 0.f, 0.f};
#pragma unroll
            for (int kt = 0; kt < 2; kt++) {
                const __half* wb = W2h + (nt * 8 + gid) * SW2 + kt * 16 + qc;
                unsigned b0 = *(const unsigned*)(wb);
                unsigned b1 = *(const unsigned*)(wb + 8);
                mma16816(c0, aF[0][kt], b0, b1);
                mma16816(c1, aF[1][kt], b0, b1);
            }
            int n0 = nt * 8 + qc;
            if (n0 < 50) {
                int i0 = (n0 < 25) ? n0 : n0 - 25;
                int i1 = (n0 + 1 < 25) ? n0 + 1 : n0 - 24;
#pragma unroll
                for (int mt = 0; mt < 2; mt++) {
                    const float* cc = mt ? c1 : c0;
                    int r = RB + mt * 16 + gid;
                    float v0 = tanhS(cc[0]) + __half2float(A1[r * SA + i0]);
                    float v1 = tanhS(cc[1]) + __half2float(A1[r * SA + i1]);
                    *(__half2*)(Y2 + r * SY + n0) = __floats2half2_rn(v0, v1);
                    r += 8;
                    float v2 = tanhS(cc[2]) + __half2float(A1[r * SA + i0]);
                    float v3 = tanhS(cc[3]) + __half2float(A1[r * SA + i1]);
                    *(__half2*)(Y2 + r * SY + n0) = __floats2half2_rn(v2, v3);
                }
            }
        }
    }
    __syncthreads();

    // ---- layer 3 GEMM: out[128x100] = tanh(Y2[128x51] * W3^T) + concat(y2,y2) ----
    {
        unsigned aG[2][4][4];
#pragma unroll
        for (int mt = 0; mt < 2; mt++)
#pragma unroll
            for (int kt = 0; kt < 4; kt++) {
                const __half* base = Y2 + (RB + mt * 16 + gid) * SY + kt * 16 + qc;
                aG[mt][kt][0] = *(const unsigned*)(base);
                aG[mt][kt][1] = *(const unsigned*)(base + 8 * SY);
                aG[mt][kt][2] = *(const unsigned*)(base + 8);
                aG[mt][kt][3] = *(const unsigned*)(base + 8 * SY + 8);
            }
        const size_t gbase = (size_t)blockIdx.x * 128;  // sample-major output rows
#pragma unroll
        for (int nt = 0; nt < 13; nt++) {
            float c0[4] = {0.f, 0.f, 0.f, 0.f};
            float c1[4] = {0.f, 0.f, 0.f, 0.f};
#pragma unroll
            for (int kt = 0; kt < 4; kt++) {
                const __half* wb = W3h + (nt * 8 + gid) * SW3 + kt * 16 + qc;
                unsigned b0 = *(const unsigned*)(wb);
                unsigned b1 = *(const unsigned*)(wb + 8);
                mma16816(c0, aG[0][kt], b0, b1);
                mma16816(c1, aG[1][kt], b0, b1);
            }
            int n0 = nt * 8 + qc;
            if (n0 < 100) {
                int i0 = (n0 < 50) ? n0 : n0 - 50;
                int i1 = (n0 + 1 < 50) ? n0 + 1 : n0 - 49;
#pragma unroll
                for (int mt = 0; mt < 2; mt++) {
                    const float* cc = mt ? c1 : c0;
                    int r = RB + mt * 16 + gid;
                    float v0 = tanhS(cc[0]) + __half2float(Y2[r * SY + i0]);
                    float v1 = tanhS(cc[1]) + __half2float(Y2[r * SY + i1]);
                    *(__half2*)(g_out + (gbase + r) * 100 + n0) = __floats2half2_rn(v0, v1);
                    r += 8;
                    float v2 = tanhS(cc[2]) + __half2float(Y2[r * SY + i0]);
                    float v3 = tanhS(cc[3]) + __half2float(Y2[r * SY + i1]);
                    *(__half2*)(g_out + (gbase + r) * 100 + n0) = __floats2half2_rn(v2, v3);
                }
            }
        }
    }
}

// ---------------- K2: res[g][f] = sum_a M[g][a]*M[f][a], M = out^T * a ----------------
__global__ __launch_bounds__(128)
void k2_contract(const float* __restrict__ coords, float* __restrict__ outp) {
    __shared__ float cs[NCAT * 3];
    __shared__ float as_[NK * 3];
    __shared__ int   sk[NK];
    __shared__ float Mpart[4][25][12];
    __shared__ float Ms[100 * 3];

    const int n   = blockIdx.x;
    const int b   = blockIdx.y;
    const int tid = threadIdx.x;
    const int warp = tid >> 5, lane = tid & 31;
    const int half = b >> 5, bl = b & 31;

    for (int i = tid; i < NCAT * 3; i += 128)
        cs[i] = coords[(size_t)b * NCAT * 3 + i];
    if (tid < NK)
        sk[tid] = g_sinv[(n * NK + tid) * 2 + half] * 32 + bl;
    __syncthreads();

    if (tid < NK) {
        int k = tid;
        int j = k + (k >= n ? 1 : 0);
        float rx = cs[n * 3 + 0] - cs[j * 3 + 0];
        float ry = cs[n * 3 + 1] - cs[j * 3 + 1];
        float rz = cs[n * 3 + 2] - cs[j * 3 + 2];
        float d  = sqrtf(rx * rx + ry * ry + rz * rz);
        float dinv = 1.0f / fmaxf(d, 1e-12f);
        float s = dinv * dinv;
        as_[k * 3 + 0] = rx * s;
        as_[k * 3 + 1] = ry * s;
        as_[k * 3 + 2] = rz * s;
    }
    __syncthreads();

    float acc[12];
#pragma unroll
    for (int i = 0; i < 12; i++) acc[i] = 0.0f;

    if (lane < 25) {
        for (int kk = warp; kk < NK; kk += 4) {
            uint2 pr = *(const uint2*)(g_out + (size_t)sk[kk] * 100 + lane * 4);
            __half2 h01 = *(__half2*)&pr.x;
            __half2 h23 = *(__half2*)&pr.y;
            float2 f01 = __half22float2(h01);
            float2 f23 = __half22float2(h23);
            float a0 = as_[kk * 3 + 0];
            float a1 = as_[kk * 3 + 1];
            float a2 = as_[kk * 3 + 2];
            acc[0]  = fmaf(f01.x, a0, acc[0]);
            acc[1]  = fmaf(f01.x, a1, acc[1]);
            acc[2]  = fmaf(f01.x, a2, acc[2]);
            acc[3]  = fmaf(f01.y, a0, acc[3]);
            acc[4]  = fmaf(f01.y, a1, acc[4]);
            acc[5]  = fmaf(f01.y, a2, acc[5]);
            acc[6]  = fmaf(f23.x, a0, acc[6]);
            acc[7]  = fmaf(f23.x, a1, acc[7]);
            acc[8]  = fmaf(f23.x, a2, acc[8]);
            acc[9]  = fmaf(f23.y, a0, acc[9]);
            acc[10] = fmaf(f23.y, a1, acc[10]);
            acc[11] = fmaf(f23.y, a2, acc[11]);
        }
#pragma unroll
        for (int i = 0; i < 12; i++) Mpart[warp][lane][i] = acc[i];
    }
    __syncthreads();

    float m0 = 0.0f, m1 = 0.0f, m2 = 0.0f;
    if (tid < 100) {
        const int quad = tid >> 2, e = tid & 3;
#pragma unroll
        for (int w = 0; w < 4; w++) {
            m0 += Mpart[w][quad][e * 3 + 0];
            m1 += Mpart[w][quad][e * 3 + 1];
            m2 += Mpart[w][quad][e * 3 + 2];
        }
        Ms[tid * 3 + 0] = m0;
        Ms[tid * 3 + 1] = m1;
        Ms[tid * 3 + 2] = m2;
    }
    __syncthreads();

    if (tid < 100) {
        float4 r;
        r.x = m0 * Ms[0] + m1 * Ms[1]  + m2 * Ms[2];
        r.y = m0 * Ms[3] + m1 * Ms[4]  + m2 * Ms[5];
        r.z = m0 * Ms[6] + m1 * Ms[7]  + m2 * Ms[8];
        r.w = m0 * Ms[9] + m1 * Ms[10] + m2 * Ms[11];
        *(float4*)(outp + ((size_t)(b * NCAT + n)) * 400 + tid * 4) = r;
    }
}

extern "C" void kernel_launch(void* const* d_in, const int* in_sizes, int n_in,
                              void* d_out, int out_size) {
    const float* coords     = (const float*)d_in[0];
    const int*   atom_types = (const int*)d_in[1];
    const float* W1 = (const float*)d_in[2];
    const float* b1 = (const float*)d_in[3];
    const float* W2 = (const float*)d_in[4];
    const float* b2 = (const float*)d_in[5];
    const float* W3 = (const float*)d_in[6];
    const float* b3 = (const float*)d_in[7];
    float* outp = (float*)d_out;

    prep_packh<<<1024, 256>>>(W1, b1, W2, b2, W3, b3);
    prep_plan<<<1, 256>>>(atom_types);
    k1_mlp<<<NBLK1, 128>>>(coords, atom_types);
    k2_contract<<<dim3(NCAT, NBATCH), 128>>>(coords, outp);
}